// round 1
// baseline (speedup 1.0000x reference)
#include <cuda_runtime.h>

// ---------------------------------------------------------------------------
// AdaptiveUnivariateFunction: out = linear_spline(normalize(x); cp, uniform knots)
//   xn  = (x - min(x)) / (max(x) - min(x) + 1e-6)      -> always in [0, 1)
//   idx = clamp(floor(xn * 31), 0, 30)
//   t   = xn*31 - idx
//   out = cp[idx] + t * (cp[idx+1] - cp[idx])
// Two-phase: (1) global min/max reduction, (2) elementwise transform.
// ---------------------------------------------------------------------------

__device__ unsigned int g_min_u;   // flipped-uint encoding of running min
__device__ unsigned int g_max_u;   // flipped-uint encoding of running max

// Order-preserving float <-> uint transform (monotone under unsigned compare)
__device__ __forceinline__ unsigned int flipf(float f) {
    unsigned int u = __float_as_uint(f);
    return u ^ ((unsigned int)(-(int)(u >> 31)) | 0x80000000u);
}
__device__ __forceinline__ float unflipf(unsigned int u) {
    return __uint_as_float(u ^ (((u >> 31) - 1u) | 0x80000000u));
}

__global__ void auf_init_kernel() {
    g_min_u = 0xFFFFFFFFu;   // +inf in flipped space
    g_max_u = 0u;            // -inf in flipped space
}

// ---------------------------------------------------------------------------
// Pass 1: global min/max. Ascending order so the tail of x stays L2-resident
// for pass 2 (which walks descending). Default cache policy (keep in L2).
// ---------------------------------------------------------------------------
__global__ void __launch_bounds__(256, 8)
auf_minmax_kernel(const float* __restrict__ xs, int n) {
    const float4* __restrict__ x4 = (const float4*)xs;
    const int nv4 = n >> 2;

    float vmin = 3.402823466e38f;
    float vmax = -3.402823466e38f;

    const int stride = gridDim.x * blockDim.x;
    for (int i = blockIdx.x * blockDim.x + threadIdx.x; i < nv4; i += stride) {
        float4 v = x4[i];
        vmin = fminf(vmin, fminf(fminf(v.x, v.y), fminf(v.z, v.w)));
        vmax = fmaxf(vmax, fmaxf(fmaxf(v.x, v.y), fmaxf(v.z, v.w)));
    }
    // scalar tail (defensive; n is divisible by 4 for this problem)
    if (blockIdx.x == 0 && threadIdx.x < (n & 3)) {
        float v = xs[(nv4 << 2) + threadIdx.x];
        vmin = fminf(vmin, v);
        vmax = fmaxf(vmax, v);
    }

    // warp reduce
    #pragma unroll
    for (int o = 16; o; o >>= 1) {
        vmin = fminf(vmin, __shfl_xor_sync(0xFFFFFFFFu, vmin, o));
        vmax = fmaxf(vmax, __shfl_xor_sync(0xFFFFFFFFu, vmax, o));
    }

    // block reduce
    __shared__ float smin[8], smax[8];
    const int wid = threadIdx.x >> 5;
    const int lid = threadIdx.x & 31;
    if (lid == 0) { smin[wid] = vmin; smax[wid] = vmax; }
    __syncthreads();
    if (threadIdx.x == 0) {
        float bmin = smin[0], bmax = smax[0];
        const int nw = blockDim.x >> 5;
        #pragma unroll
        for (int w = 1; w < 8; w++) {
            if (w < nw) { bmin = fminf(bmin, smin[w]); bmax = fmaxf(bmax, smax[w]); }
        }
        atomicMin(&g_min_u, flipf(bmin));
        atomicMax(&g_max_u, flipf(bmax));
    }
}

// ---------------------------------------------------------------------------
// Pass 2: spline transform. Walks DESCENDING so it first touches what pass 1
// read last (L2 hits). .cs loads/stores: x lines are dead after one read,
// out lines are never re-read -> evict-first, minimize L2 thrash.
// ---------------------------------------------------------------------------
__device__ __forceinline__ float auf_eval(float x, float S, float B,
                                          const float2* __restrict__ tab) {
    float xn31 = fmaf(x, S, B);          // xn * 31
    int idx = (int)xn31;                 // trunc == floor (xn31 >= -eps)
    idx = max(0, min(idx, 30));          // safety clamp (continuity makes
                                         // boundary rounding value-neutral)
    float2 ad = tab[idx];                // (cp[idx], cp[idx+1]-cp[idx])
    return fmaf(xn31 - (float)idx, ad.y, ad.x);
}

__global__ void __launch_bounds__(256, 8)
auf_apply_kernel(const float* __restrict__ xs,
                 const float* __restrict__ cp,
                 float* __restrict__ outs,
                 int n) {
    __shared__ float2 tab[32];
    if (threadIdx.x < 32) {
        int i = (threadIdx.x < 31) ? (int)threadIdx.x : 30;  // slot 31 = dup of 30
        float c0 = cp[i];
        float c1 = cp[i + 1];
        tab[threadIdx.x] = make_float2(c0, c1 - c0);
    }

    const float xmin = unflipf(g_min_u);
    const float xmax = unflipf(g_max_u);
    const float S = 31.0f / (xmax - xmin + 1e-6f);
    const float B = -xmin * S;
    __syncthreads();

    const float4* __restrict__ x4 = (const float4*)xs;
    float4* __restrict__ o4 = (float4*)outs;
    const int nv4 = n >> 2;

    const int stride = gridDim.x * blockDim.x;
    for (int i = blockIdx.x * blockDim.x + threadIdx.x; i < nv4; i += stride) {
        const int j = nv4 - 1 - i;       // reversed traversal for L2 reuse
        float4 v = __ldcs(&x4[j]);
        float4 r;
        r.x = auf_eval(v.x, S, B, tab);
        r.y = auf_eval(v.y, S, B, tab);
        r.z = auf_eval(v.z, S, B, tab);
        r.w = auf_eval(v.w, S, B, tab);
        __stcs(&o4[j], r);
    }
    // scalar tail
    if (blockIdx.x == gridDim.x - 1 && threadIdx.x < (n & 3)) {
        const int e = (nv4 << 2) + threadIdx.x;
        outs[e] = auf_eval(xs[e], S, B, tab);
    }
}

// ---------------------------------------------------------------------------
// Launch: init -> minmax -> apply. All default-stream kernel launches,
// no sync, no allocation -> graph-capturable.
// ---------------------------------------------------------------------------
extern "C" void kernel_launch(void* const* d_in, const int* in_sizes, int n_in,
                              void* d_out, int out_size) {
    const float* x  = (const float*)d_in[0];   // (64, 1048576) fp32
    const float* cp = (const float*)d_in[1];   // (32,) control points
    // d_in[2] = knots: uniform linspace(0,1,32) by construction -> not needed
    const int n = in_sizes[0];

    const int threads = 256;
    const int blocks  = 1184;   // 148 SMs * 8 resident blocks: one full wave

    auf_init_kernel<<<1, 1>>>();
    auf_minmax_kernel<<<blocks, threads>>>(x, n);
    auf_apply_kernel<<<blocks, threads>>>(x, cp, (float*)d_out, n);
}